// round 5
// baseline (speedup 1.0000x reference)
#include <cuda_runtime.h>
#include <cstdint>

#define D_DIM   128
#define K_CODES 1024
#define N_MAX   131072
#define BM      128
#define BN      128
#define NTHR    256
#define XDP     129   // xdup pitch in ull units (pad: conflict-free xn column reads)
#define CP      128   // cs pitch in floats

typedef unsigned long long ull;

// -------- device scratch --------
__device__ int   g_idx[N_MAX];
__device__ float g_cnorm[K_CODES];
__device__ float g_cbT[D_DIM * K_CODES];   // codebook transposed, d-major
__device__ float g_sse;
__device__ int   g_hist[K_CODES];

__device__ __forceinline__ ull pack2(float a, float b) {
    return (ull)__float_as_uint(a) | ((ull)__float_as_uint(b) << 32);
}
__device__ __forceinline__ float lo_f(ull v) { return __uint_as_float((unsigned)v); }
__device__ __forceinline__ float hi_f(ull v) { return __uint_as_float((unsigned)(v >> 32)); }

// packed fp32x2 FMA: each lane is IEEE-RN fp32, identical to fmaf per lane
__device__ __forceinline__ void ffma2(ull& acc, ull a, ull b) {
    asm("fma.rn.f32x2 %0, %1, %2, %0;" : "+l"(acc) : "l"(a), "l"(b));
}

// XLA warp row-reduce: shfl_down tree, offsets 16/8/4/2/1, fp32 add each step.
__device__ __forceinline__ float xla_warp_reduce_add(float v) {
    v = __fadd_rn(v, __shfl_down_sync(0xFFFFFFFFu, v, 16));
    v = __fadd_rn(v, __shfl_down_sync(0xFFFFFFFFu, v, 8));
    v = __fadd_rn(v, __shfl_down_sync(0xFFFFFFFFu, v, 4));
    v = __fadd_rn(v, __shfl_down_sync(0xFFFFFFFFu, v, 2));
    v = __fadd_rn(v, __shfl_down_sync(0xFFFFFFFFu, v, 1));
    return v;
}

// ============================================================
// K0: c_norm (XLA emulation) + transpose codebook + zero scalars/hist
// ============================================================
__global__ void prep_kernel(const float* __restrict__ cb) {
    if (blockIdx.x == 0) {
        if (threadIdx.x == 0) g_sse = 0.0f;
        for (int i = threadIdx.x; i < K_CODES; i += blockDim.x) g_hist[i] = 0;
    }
    int lane  = threadIdx.x & 31;
    int code  = blockIdx.x * (blockDim.x >> 5) + (threadIdx.x >> 5);
    if (code >= K_CODES) return;
    const float* row = cb + (size_t)code * D_DIM;

    const float4* row4 = (const float4*)row;
    float4 v = row4[lane];
    g_cbT[(lane * 4 + 0) * K_CODES + code] = v.x;
    g_cbT[(lane * 4 + 1) * K_CODES + code] = v.y;
    g_cbT[(lane * 4 + 2) * K_CODES + code] = v.z;
    g_cbT[(lane * 4 + 3) * K_CODES + code] = v.w;

    float e0 = row[lane], e1 = row[lane + 32], e2 = row[lane + 64], e3 = row[lane + 96];
    float p = __fmul_rn(e0, e0);
    p = __fadd_rn(p, __fmul_rn(e1, e1));
    p = __fadd_rn(p, __fmul_rn(e2, e2));
    p = __fadd_rn(p, __fmul_rn(e3, e3));
    float s = xla_warp_reduce_add(p);
    if (lane == 0) g_cnorm[code] = s;
}

// ============================================================
// KA: fused exact scores-GEMM (FFMA2-packed, per-lane d-ascending chain)
//     + reference-faithful quantized dist + first-index argmin.
// ============================================================
__global__ __launch_bounds__(NTHR, 1)
void argmin_kernel(const float* __restrict__ x) {
    extern __shared__ char smem_raw[];
    ull*   xd = (ull*)smem_raw;                           // [D][XDP] duplicated (x,x)
    float* cs = (float*)(smem_raw + D_DIM * XDP * 8);     // [D][CP]
    float* cn = cs + D_DIM * CP;                          // [BN]
    float* xn = cn + BN;                                  // [BM]

    const int tid = threadIdx.x;
    const int tx  = tid & 15;            // col-pair group
    const int ty  = tid >> 4;            // row group
    const int lane = tid & 31, warp = tid >> 5;
    const size_t row0 = (size_t)blockIdx.x * BM;

    // ---- load x tile, transposed + duplicated into xd[d][r] = (x,x) ----
    const float4* x4 = (const float4*)(x + row0 * D_DIM);
    for (int i = tid; i < BM * (D_DIM / 4); i += NTHR) {
        int r = i >> 5, d4 = i & 31;
        float4 v = x4[r * (D_DIM / 4) + d4];
        xd[(d4 * 4 + 0) * XDP + r] = pack2(v.x, v.x);
        xd[(d4 * 4 + 1) * XDP + r] = pack2(v.y, v.y);
        xd[(d4 * 4 + 2) * XDP + r] = pack2(v.z, v.z);
        xd[(d4 * 4 + 3) * XDP + r] = pack2(v.w, v.w);
    }
    __syncthreads();

    // ---- x_norm per row, XLA emulation (warp w: rows 16w..16w+15) ----
    const float* fxd = (const float*)xd;
    for (int k = 0; k < 16; k++) {
        int r = warp * 16 + k;
        float e0 = fxd[2 * (lane * XDP + r)];
        float e1 = fxd[2 * ((lane + 32) * XDP + r)];
        float e2 = fxd[2 * ((lane + 64) * XDP + r)];
        float e3 = fxd[2 * ((lane + 96) * XDP + r)];
        float p = __fmul_rn(e0, e0);
        p = __fadd_rn(p, __fmul_rn(e1, e1));
        p = __fadd_rn(p, __fmul_rn(e2, e2));
        p = __fadd_rn(p, __fmul_rn(e3, e3));
        float s = xla_warp_reduce_add(p);
        if (lane == 0) xn[r] = s;
    }

    float best[8];
    int   bidx[8];
    #pragma unroll
    for (int i = 0; i < 8; i++) { best[i] = 3.4e38f; bidx[i] = 0x7FFFFFFF; }

    float xni[8];

    for (int t = 0; t < K_CODES / BN; t++) {
        for (int i = tid; i < D_DIM * (BN / 4); i += NTHR) {
            int d = i >> 5, c4 = i & 31;
            float4 v = *(const float4*)&g_cbT[d * K_CODES + t * BN + c4 * 4];
            *(float4*)&cs[d * CP + c4 * 4] = v;
        }
        if (tid < BN) cn[tid] = g_cnorm[t * BN + tid];
        __syncthreads();   // also covers xn writes on t==0

        if (t == 0) {
            #pragma unroll
            for (int i = 0; i < 8; i++) xni[i] = xn[ty + 16 * i];
        }

        ull acc[8][4];
        #pragma unroll
        for (int i = 0; i < 8; i++)
            #pragma unroll
            for (int p = 0; p < 4; p++) acc[i][p] = 0ull;

        #pragma unroll 4
        for (int d = 0; d < D_DIM; d++) {
            const ull* xrow = xd + d * XDP;
            const ull* crow = (const ull*)(cs + d * CP);
            ull xf[8], cf[4];
            #pragma unroll
            for (int i = 0; i < 8; i++) xf[i] = xrow[ty + 16 * i];
            #pragma unroll
            for (int p = 0; p < 4; p++) cf[p] = crow[tx + 16 * p];
            #pragma unroll
            for (int i = 0; i < 8; i++)
                #pragma unroll
                for (int p = 0; p < 4; p++)
                    ffma2(acc[i][p], xf[i], cf[p]);   // both lanes: exact d-chain
        }

        // ---- quantized dist + running first-index argmin ----
        #pragma unroll
        for (int p = 0; p < 4; p++) {
            int cp = tx + 16 * p;
            #pragma unroll
            for (int h = 0; h < 2; h++) {
                int   col  = 2 * cp + h;
                float cnj  = cn[col];
                int   code = t * BN + col;
                #pragma unroll
                for (int i = 0; i < 8; i++) {
                    float s    = h ? hi_f(acc[i][p]) : lo_f(acc[i][p]);
                    float tt   = __fadd_rn(xni[i], cnj);           // fl(xn + cn)
                    float u    = __fmul_rn(2.0f, s);               // exact
                    float dist = fmaxf(__fadd_rn(tt, -u), 0.0f);   // fl(t - 2s), clamp
                    if (dist < best[i]) { best[i] = dist; bidx[i] = code; }
                }
            }
        }
        __syncthreads();
    }

    // ---- cross-thread reduction (16 candidates per row), lexicographic ----
    float* rv = cs;
    int*   ri = (int*)(cs + BM * 16);
    #pragma unroll
    for (int i = 0; i < 8; i++) {
        int r = ty + 16 * i;
        rv[r * 16 + tx] = best[i];
        ri[r * 16 + tx] = bidx[i];
    }
    __syncthreads();
    if (tid < BM) {
        float bv = rv[tid * 16];
        int   bi = ri[tid * 16];
        #pragma unroll
        for (int k = 1; k < 16; k++) {
            float v  = rv[tid * 16 + k];
            int   id = ri[tid * 16 + k];
            if (v < bv || (v == bv && id < bi)) { bv = v; bi = id; }
        }
        g_idx[row0 + tid] = bi;
    }
}

// ============================================================
// KB: gather z, emit z_st = fl(x + fl(z - x)), accumulate SSE
// ============================================================
__global__ void gather_kernel(const float* __restrict__ x,
                              const float* __restrict__ cb,
                              float* __restrict__ out, int n) {
    int i4 = blockIdx.x * blockDim.x + threadIdx.x;
    float local = 0.0f;
    int total4 = n * (D_DIM / 4);
    if (i4 < total4) {
        int row = i4 >> 5;
        int c4  = i4 & 31;
        int idx = g_idx[row];
        float4 cv = ((const float4*)cb)[idx * (D_DIM / 4) + c4];
        float4 xv = ((const float4*)x)[i4];
        float dx = __fadd_rn(cv.x, -xv.x);
        float dy = __fadd_rn(cv.y, -xv.y);
        float dz = __fadd_rn(cv.z, -xv.z);
        float dw = __fadd_rn(cv.w, -xv.w);
        float4 ov;
        ov.x = __fadd_rn(xv.x, dx);
        ov.y = __fadd_rn(xv.y, dy);
        ov.z = __fadd_rn(xv.z, dz);
        ov.w = __fadd_rn(xv.w, dw);
        ((float4*)out)[i4] = ov;
        local = dx * dx + dy * dy + dz * dz + dw * dw;
    }
    #pragma unroll
    for (int off = 16; off; off >>= 1) local += __shfl_xor_sync(0xFFFFFFFFu, local, off);
    __shared__ float red[8];
    int lane = threadIdx.x & 31, warp = threadIdx.x >> 5;
    if (lane == 0) red[warp] = local;
    __syncthreads();
    if (warp == 0) {
        float v = (lane < 8) ? red[lane] : 0.0f;
        #pragma unroll
        for (int off = 4; off; off >>= 1) v += __shfl_xor_sync(0xFFFFFFFFu, v, off);
        if (lane == 0) atomicAdd(&g_sse, v);
    }
}

// ============================================================
// KC1: multi-block histogram (smem counts -> global atomics)
// ============================================================
__global__ void hist_kernel(int n) {
    __shared__ int cnt[K_CODES];
    int tid = threadIdx.x;
    for (int i = tid; i < K_CODES; i += blockDim.x) cnt[i] = 0;
    __syncthreads();
    int stride = gridDim.x * blockDim.x;
    for (int i = blockIdx.x * blockDim.x + tid; i < n; i += stride)
        atomicAdd(&cnt[g_idx[i]], 1);
    __syncthreads();
    for (int i = tid; i < K_CODES; i += blockDim.x) {
        int c = cnt[i];
        if (c) atomicAdd(&g_hist[i], c);
    }
}

// ============================================================
// KC2: perplexity + scalars
// ============================================================
__global__ void perp_kernel(float* __restrict__ out, int n, long scalar_off) {
    __shared__ float rs[32];
    int tid = threadIdx.x;
    float local = 0.0f;
    float invn = 1.0f / (float)n;
    for (int i = tid; i < K_CODES; i += blockDim.x) {
        float p = __fmul_rn((float)g_hist[i], invn);
        local += p * logf(__fadd_rn(p, 1e-10f));
    }
    #pragma unroll
    for (int off = 16; off; off >>= 1) local += __shfl_xor_sync(0xFFFFFFFFu, local, off);
    int lane = tid & 31, warp = tid >> 5;
    if (lane == 0) rs[warp] = local;
    __syncthreads();
    if (warp == 0) {
        float v = (lane < (int)(blockDim.x >> 5)) ? rs[lane] : 0.0f;
        #pragma unroll
        for (int off = 16; off; off >>= 1) v += __shfl_xor_sync(0xFFFFFFFFu, v, off);
        if (lane == 0) {
            float loss = g_sse / (float)((long)n * D_DIM);
            out[scalar_off + 0] = loss;        // quantization_loss
            out[scalar_off + 1] = loss;        // commitment_loss
            out[scalar_off + 2] = expf(-v);    // perplexity
        }
    }
}

// ============================================================
extern "C" void kernel_launch(void* const* d_in, const int* in_sizes, int n_in,
                              void* d_out, int out_size) {
    const float* x  = (const float*)d_in[0];
    const float* cb = (const float*)d_in[1];
    float* out = (float*)d_out;

    int nx = in_sizes[0];
    int n  = nx / D_DIM;

    constexpr int SMEM_KA = D_DIM * XDP * 8 + (D_DIM * CP + BN + BM) * (int)sizeof(float);
    cudaFuncSetAttribute(argmin_kernel, cudaFuncAttributeMaxDynamicSharedMemorySize, SMEM_KA);

    prep_kernel<<<K_CODES / 8, 256>>>(cb);
    argmin_kernel<<<n / BM, NTHR, SMEM_KA>>>(x);
    gather_kernel<<<(n * (D_DIM / 4) + 255) / 256, 256>>>(x, cb, out, n);
    hist_kernel<<<256, 256>>>(n);
    perp_kernel<<<1, 1024>>>(out, n, (long)nx);
}